// round 9
// baseline (speedup 1.0000x reference)
#include <cuda_runtime.h>
#include <cstdint>

// Fixed problem shape: N=320000, C=64, B=4, NY=496, NX=432, NZ=1
#define NY_   496
#define NX_   432
#define C_    64
#define B_    4
#define NCELL (B_ * NY_ * NX_)        // 857,088 cells

#define CCH    16                     // channels per chunk (4 chunks)
#define PITCH  436                    // SMEM pitch (432+4, multiple of 4)
#define THREADS_G 512

// Winner encoding: 0 = empty, w = point_index + 1.
// __device__ globals are zero-initialized at module load; the gather kernel
// re-zeroes each block's winner segment after consuming it, so the array is
// all-zero at every kernel_launch entry (identical state -> deterministic).
__device__ int4 g_winner4[NCELL / 4];

// ---------------------------------------------------------------------------
// Kernel 1: atomicMax scatter of (point index + 1). Last-write-wins == max.
// coors rows: (b, z, y, x), z == 0 always (NZ=1).
// ---------------------------------------------------------------------------
__global__ void scatter_winner_kernel(const int* __restrict__ coors, int n) {
    int i = blockIdx.x * blockDim.x + threadIdx.x;
    if (i < n) {
        int4 cz = *reinterpret_cast<const int4*>(coors + 4 * i);
        int cell = (cz.x * NY_ + cz.z) * NX_ + cz.w;
        atomicMax(reinterpret_cast<int*>(g_winner4) + cell, i + 1);
    }
}

// ---------------------------------------------------------------------------
// Kernel 2: one block per (b, y) row — 432 cells x 64 channels, 4 chunks of
// 16 channels through a transposed SMEM tile.
//   Phase 0: 432 winners -> SMEM (108 int4), then reset them to 0 in GMEM.
//   Phase 2 (per chunk): thread = cell (t < 432); 4x LDG.128 (64 B feature
//       slice, MLP=4), transpose-store 16 scalars (stride-1 STS, no conflicts).
//   Phase 3 (per chunk): warp w <-> channel cc+w (16 warps = 16 channels);
//       lanes stride the 108 float4s: LDS.128 + STG.128 (evict-first).
// Static SMEM: 432*4 + 16*436*4 = 29,632 B.
// ---------------------------------------------------------------------------
__global__ __launch_bounds__(THREADS_G) void gather_row_kernel(
    const float* __restrict__ feat, float* __restrict__ out) {

    __shared__ int   sw[NX_];              // 1.7 KB
    __shared__ float tile[CCH * PITCH];    // 27.9 KB

    int t = threadIdx.x;
    int p = blockIdx.x;                    // 0 .. B*NY-1  (1984)
    int cell0 = p * NX_;                   // contiguous winner segment

    // Phase 0: copy winners to SMEM, then zero them for the next replay.
    if (t < NX_ / 4) {
        int4 w4 = g_winner4[cell0 / 4 + t];
        *reinterpret_cast<int4*>(sw + 4 * t) = w4;
        g_winner4[cell0 / 4 + t] = make_int4(0, 0, 0, 0);
    }
    __syncthreads();

    int b = p / NY_;
    int y = p - b * NY_;
    size_t rowbase = ((size_t)(b * C_) * NY_ + y) * NX_;

    int warp = t >> 5;
    int lane = t & 31;

    #pragma unroll
    for (int cc = 0; cc < C_; cc += CCH) {
        // Phase 2: gather + transpose 16-channel slice, thread = cell
        if (t < NX_) {
            int w = sw[t];
            float4 v0 = make_float4(0.f, 0.f, 0.f, 0.f);
            float4 v1 = v0, v2 = v0, v3 = v0;
            if (w > 0) {
                const float4* src = reinterpret_cast<const float4*>(
                    feat + (size_t)(w - 1) * C_ + cc);
                v0 = src[0]; v1 = src[1]; v2 = src[2]; v3 = src[3];
            }
            tile[ 0 * PITCH + t] = v0.x;  tile[ 1 * PITCH + t] = v0.y;
            tile[ 2 * PITCH + t] = v0.z;  tile[ 3 * PITCH + t] = v0.w;
            tile[ 4 * PITCH + t] = v1.x;  tile[ 5 * PITCH + t] = v1.y;
            tile[ 6 * PITCH + t] = v1.z;  tile[ 7 * PITCH + t] = v1.w;
            tile[ 8 * PITCH + t] = v2.x;  tile[ 9 * PITCH + t] = v2.y;
            tile[10 * PITCH + t] = v2.z;  tile[11 * PITCH + t] = v2.w;
            tile[12 * PITCH + t] = v3.x;  tile[13 * PITCH + t] = v3.y;
            tile[14 * PITCH + t] = v3.z;  tile[15 * PITCH + t] = v3.w;
        }
        __syncthreads();

        // Phase 3: warp w writes channel cc+w (108 float4, 432 floats contig.)
        {
            const float* src = &tile[warp * PITCH];
            float* dst = out + rowbase + (size_t)(cc + warp) * (NY_ * NX_);
            for (int g = lane; g < NX_ / 4; g += 32) {
                float4 v = *reinterpret_cast<const float4*>(src + g * 4);
                __stcs(reinterpret_cast<float4*>(dst + g * 4), v);
            }
        }
        __syncthreads();
    }
}

// ---------------------------------------------------------------------------
extern "C" void kernel_launch(void* const* d_in, const int* in_sizes, int n_in,
                              void* d_out, int out_size) {
    const float* feat  = (const float*)d_in[0];   // [N, 64] float32
    const int*   coors = (const int*)d_in[1];     // [N, 4] int32
    (void)n_in; (void)out_size;

    int n = in_sizes[1] / 4;

    {   // 1) atomicMax (point index + 1); winner array is all-zero on entry
        int threads = 256;
        int blocks  = (n + threads - 1) / threads;
        scatter_winner_kernel<<<blocks, threads>>>(coors, n);
    }
    {   // 2) row gather + transpose (+ winner reset for next replay)
        int blocks = B_ * NY_;   // 1984
        gather_row_kernel<<<blocks, THREADS_G>>>(feat, (float*)d_out);
    }
}